// round 6
// baseline (speedup 1.0000x reference)
#include <cuda_runtime.h>

// SNN_46291157516323:  T=4096, B=4, D=1024, H=4096
// out = concat( soft[B,T] = boundary_logits^T ,  hard[B,T] = LIF spikes^T )
//
// Pipeline (4 graph-captured launches, no allocs):
//   1) zero g_logits
//   2) fused GEMM: logits[mat][m] = sum_h relu(X[m,:]·W1[:,h] + b1[h]) * W2[h]
//      (mat 0 = boundary MLP, mat 1 = reset MLP), atomicAdd split over N-tiles
//   3) soft output transpose (+ b2)
//   4) sequential LIF scan (4 chains), SMEM-staged, writes hard output

#define TT 4096
#define BB 4
#define DD 1024
#define HH 4096
#define MM (TT * BB)   // 16384 rows
#define NN (2 * HH)    // 8192 cols (both MLPs side by side)

__device__ float g_logits[2 * MM];   // [mat][m], m = t*B + b

typedef unsigned long long ull;

__device__ __forceinline__ ull ffma2(ull a, ull b, ull c) {
    ull d;
    asm("fma.rn.f32x2 %0, %1, %2, %3;" : "=l"(d) : "l"(a), "l"(b), "l"(c));
    return d;
}
__device__ __forceinline__ ull dup2(float x) {
    ull d; unsigned u = __float_as_uint(x);
    asm("mov.b64 %0, {%1, %1};" : "=l"(d) : "r"(u));
    return d;
}
__device__ __forceinline__ void unpack2(ull v, float& a, float& b) {
    unsigned ua, ub;
    asm("mov.b64 {%0, %1}, %2;" : "=r"(ua), "=r"(ub) : "l"(v));
    a = __uint_as_float(ua); b = __uint_as_float(ub);
}

// ---------------------------------------------------------------------------
// 1) zero the logits accumulator
// ---------------------------------------------------------------------------
__global__ void zero_kernel() {
    int i = blockIdx.x * 256 + threadIdx.x;
    if (i < 2 * MM) g_logits[i] = 0.0f;
}

// ---------------------------------------------------------------------------
// 2) fused GEMM + ReLU + layer-2 reduction.
//    Tile: 128(M) x 128(N) x 8(K), 256 threads, 8x8 per-thread microtile
//    packed as 4x8 f32x2 accumulators (pairs along M).
// ---------------------------------------------------------------------------
__global__ __launch_bounds__(256, 2) void gemm_kernel(
    const float* __restrict__ X,
    const float* __restrict__ Wb1, const float* __restrict__ Wr1,
    const float* __restrict__ bb1, const float* __restrict__ br1,
    const float* __restrict__ Wb2, const float* __restrict__ Wr2)
{
    __shared__ float As[8][128];   // [k][m]  (transposed X tile)
    __shared__ float Bs[8][128];   // [k][n]

    const int tid = threadIdx.x;
    const int tx  = tid & 15;      // 0..15  (N direction)
    const int ty  = tid >> 4;      // 0..15  (M direction)
    const int bm  = blockIdx.y * 128;
    const int bn  = blockIdx.x * 128;

    const int mat = (bn >= HH) ? 1 : 0;
    const int n0  = mat ? (bn - HH) : bn;
    const float* __restrict__ W1 = mat ? Wr1 : Wb1;

    // global-load assignment
    const int xrow = tid >> 1;           // 0..127
    const int xcg  = (tid & 1) * 4;      // 0 or 4
    const int wrow = tid >> 5;           // 0..7
    const int wcol = (tid & 31) * 4;     // 0..124

    const float* Xp = X  + (size_t)(bm + xrow) * DD + xcg;
    const float* Wp = W1 + (size_t)wrow * HH + n0 + wcol;

    ull acc[4][8];
    #pragma unroll
    for (int i = 0; i < 4; i++)
        #pragma unroll
        for (int j = 0; j < 8; j++) acc[i][j] = 0ull;

    float4 xf = *(const float4*)Xp;
    float4 wf = *(const float4*)Wp;

    for (int k0 = 0; k0 < DD; k0 += 8) {
        // stage current tiles
        As[xcg + 0][xrow] = xf.x;
        As[xcg + 1][xrow] = xf.y;
        As[xcg + 2][xrow] = xf.z;
        As[xcg + 3][xrow] = xf.w;
        *(float4*)&Bs[wrow][wcol] = wf;
        __syncthreads();

        // prefetch next tiles (overlaps with compute below)
        if (k0 + 8 < DD) {
            xf = *(const float4*)(Xp + (k0 + 8));
            wf = *(const float4*)(Wp + (size_t)(k0 + 8) * HH);
        }

        #pragma unroll
        for (int k = 0; k < 8; k++) {
            ulonglong2 a01 = *(const ulonglong2*)&As[k][ty * 8];
            ulonglong2 a23 = *(const ulonglong2*)&As[k][ty * 8 + 4];
            float4 bA = *(const float4*)&Bs[k][tx * 8];
            float4 bB = *(const float4*)&Bs[k][tx * 8 + 4];
            ull a2[4] = {a01.x, a01.y, a23.x, a23.y};   // row pairs (2i, 2i+1)
            float bv[8] = {bA.x, bA.y, bA.z, bA.w, bB.x, bB.y, bB.z, bB.w};
            #pragma unroll
            for (int j = 0; j < 8; j++) {
                ull bd = dup2(bv[j]);
                #pragma unroll
                for (int i = 0; i < 4; i++)
                    acc[i][j] = ffma2(a2[i], bd, acc[i][j]);
            }
        }
        __syncthreads();
    }

    // --- epilogue: +b1, relu, *W2, reduce over this block's 128 columns ---
    const float* __restrict__ b1 = mat ? br1 : bb1;
    const float* __restrict__ W2 = mat ? Wr2 : Wb2;

    float w2v[8], b1v[8];
    #pragma unroll
    for (int j = 0; j < 8; j++) {
        int n = n0 + tx * 8 + j;
        w2v[j] = W2[n];
        b1v[j] = b1[n];
    }

    float part[8];                       // per local row r = 2i + {0,1}
    #pragma unroll
    for (int r = 0; r < 8; r++) part[r] = 0.0f;

    #pragma unroll
    for (int i = 0; i < 4; i++)
        #pragma unroll
        for (int j = 0; j < 8; j++) {
            float lo, hi;
            unpack2(acc[i][j], lo, hi);
            lo += b1v[j]; hi += b1v[j];
            part[2 * i]     += fmaxf(lo, 0.0f) * w2v[j];
            part[2 * i + 1] += fmaxf(hi, 0.0f) * w2v[j];
        }

    // reduce over the 16 tx lanes (width-16 halves of each warp)
    #pragma unroll
    for (int r = 0; r < 8; r++) {
        #pragma unroll
        for (int o = 8; o > 0; o >>= 1)
            part[r] += __shfl_down_sync(0xffffffffu, part[r], o, 16);
    }
    if (tx == 0) {
        #pragma unroll
        for (int r = 0; r < 8; r++)
            atomicAdd(&g_logits[mat * MM + bm + ty * 8 + r], part[r]);
    }
}

// ---------------------------------------------------------------------------
// 3) soft output: out[b*T + t] = boundary_logits[t*B + b] + bb2
// ---------------------------------------------------------------------------
__global__ void soft_kernel(const float* __restrict__ bb2, float* __restrict__ out) {
    int i = blockIdx.x * 256 + threadIdx.x;
    if (i < MM) {
        int b = i >> 12;           // / TT
        int t = i & (TT - 1);
        out[i] = g_logits[t * BB + b] + bb2[0];
    }
}

// ---------------------------------------------------------------------------
// 4) LIF scan: 4 serial chains, inputs staged through SMEM in tiles of 512 t.
//    v' = v + (x - v)/2 ; spike = (v' >= 1) ; hard reset ; forced reset if
//    sigmoid(r) > 0.5  <=>  r > 0.
// ---------------------------------------------------------------------------
__global__ void scan_kernel(const float* __restrict__ bb2,
                            const float* __restrict__ br2,
                            float* __restrict__ out_hard) {
    __shared__ float sx[512 * BB];
    __shared__ float sr[512 * BB];
    const int tid = threadIdx.x;
    const float b2 = bb2[0], r2 = br2[0];
    float v = 0.0f;

    for (int t0 = 0; t0 < TT; t0 += 512) {
        __syncthreads();
        for (int i = tid; i < 512 * BB; i += 128) {
            sx[i] = g_logits[t0 * BB + i];
            sr[i] = g_logits[MM + t0 * BB + i];
        }
        __syncthreads();
        if (tid < BB) {
            #pragma unroll 4
            for (int tt = 0; tt < 512; tt++) {
                float x  = sx[tt * BB + tid] + b2;
                bool  rm = (sr[tt * BB + tid] + r2) > 0.0f;
                v = v + (x - v) * 0.5f;                 // leaky integrate (tau=2)
                float s = (v >= 1.0f) ? 1.0f : 0.0f;    // fire
                out_hard[tid * TT + t0 + tt] = s;
                if (v >= 1.0f) v = 0.0f;                // hard reset on spike
                if (rm)        v = 0.0f;                // conditional forced reset
            }
        }
    }
}

// ---------------------------------------------------------------------------
extern "C" void kernel_launch(void* const* d_in, const int* in_sizes, int n_in,
                              void* d_out, int out_size) {
    const float* hidden = (const float*)d_in[0];
    const float* Wb1    = (const float*)d_in[1];
    const float* bb1    = (const float*)d_in[2];
    const float* Wb2    = (const float*)d_in[3];
    const float* bb2    = (const float*)d_in[4];
    const float* Wr1    = (const float*)d_in[5];
    const float* br1    = (const float*)d_in[6];
    const float* Wr2    = (const float*)d_in[7];
    const float* br2    = (const float*)d_in[8];
    float* out = (float*)d_out;

    zero_kernel<<<(2 * MM + 255) / 256, 256>>>();

    dim3 grid(NN / 128, MM / 128);   // (64, 128) = 8192 CTAs
    gemm_kernel<<<grid, 256>>>(hidden, Wb1, Wr1, bb1, br1, Wb2, Wr2);

    soft_kernel<<<MM / 256, 256>>>(bb2, out);
    scan_kernel<<<1, 128>>>(bb2, br2, out + MM);
}

// round 10
// speedup vs baseline: 1.2555x; 1.2555x over previous
#include <cuda_runtime.h>

// SNN_46291157516323:  T=4096, B=4, D=1024, H=4096
// 3xTF32 error-compensated GEMM via warp-level mma.sync.m16n8k8.tf32
// (tcgen05 is rejected by this harness's compute_103 virtual arch).
//
// Launch sequence (graph-captured, no allocs):
//   1) zero g_logits
//   2) prep_w : transpose W1 -> g_WT [n][k] fp32 (n = boundary || reset)
//   3) gemm   : 128x128 CTA tile, K-chunk 32, double-buffered SMEM,
//               hi/lo split at staging, 3 HMMA passes, fused
//               ReLU + layer-2 reduction epilogue -> atomicAdd logits
//   4) soft output transpose (+bb2)
//   5) sequential LIF scan (4 chains)

#define TT 4096
#define BB 4
#define DD 1024
#define HH 4096
#define MM (TT * BB)     // 16384
#define NN (2 * HH)      // 8192

#define STRIDE 36                  // 32 + 4 pad floats (conflict-free frags)
#define TILEBUF (128 * STRIDE)     // 4608 floats per tile buffer
#define STAGE   (4 * TILEBUF)      // Ahi,Alo,Bhi,Blo = 18432 floats
#define SMEM_BYTES (2 * STAGE * 4) // 147456

__device__ float g_logits[2 * MM];
__device__ float g_WT[(size_t)NN * DD];   // [n][k], k contiguous

typedef unsigned int u32;

// truncate fp32 to tf32-exact (mask low 13 mantissa bits)
__device__ __forceinline__ float tr(float x) {
    return __uint_as_float(__float_as_uint(x) & 0xffffe000u);
}

// D += A(m16k8, tf32) * B(k8n8, tf32)
__device__ __forceinline__ void mma8(float* d, const float* a, float b0, float b1) {
    asm volatile(
        "mma.sync.aligned.m16n8k8.row.col.f32.tf32.tf32.f32 "
        "{%0,%1,%2,%3}, {%4,%5,%6,%7}, {%8,%9}, {%0,%1,%2,%3};"
        : "+f"(d[0]), "+f"(d[1]), "+f"(d[2]), "+f"(d[3])
        : "r"(__float_as_uint(a[0])), "r"(__float_as_uint(a[1])),
          "r"(__float_as_uint(a[2])), "r"(__float_as_uint(a[3])),
          "r"(__float_as_uint(b0)),  "r"(__float_as_uint(b1)));
}

// ---------------------------------------------------------------- 1) zero
__global__ void zero_kernel() {
    int i = blockIdx.x * 256 + threadIdx.x;
    if (i < 2 * MM) g_logits[i] = 0.0f;
}

// ---------------------------------------------------------------- 2) prep W
// g_WT[n][k] = W[k][n];  n in [0,8192) = boundary(0..4095) || reset(4096..8191)
__global__ void prep_w(const float* __restrict__ Wb1, const float* __restrict__ Wr1) {
    __shared__ float tsm[32][33];
    int n0 = blockIdx.x * 32;
    int k0 = blockIdx.y * 32;
    const float* W = (n0 < HH) ? Wb1 : Wr1;
    int h0 = n0 & (HH - 1);
    int tx = threadIdx.x & 31, ty = threadIdx.x >> 5;   // 32 x 8
    #pragma unroll
    for (int r = 0; r < 4; r++)
        tsm[tx][ty + r * 8] = W[(size_t)(k0 + ty + r * 8) * HH + h0 + tx];
    __syncthreads();
    #pragma unroll
    for (int r = 0; r < 4; r++)
        g_WT[(size_t)(n0 + ty + r * 8) * DD + k0 + tx] = tsm[ty + r * 8][tx];
}

// ---------------------------------------------------------------- 3) GEMM
__device__ __forceinline__ void ldg_chunk(float4 a[4], float4 b[4],
                                          const float* __restrict__ X,
                                          int bm, int bn, int c, int tid) {
    const int r = tid >> 1, cb = (tid & 1) * 16;
    const float* xa = X    + (size_t)(bm + r) * DD + c * 32 + cb;
    const float* wb = g_WT + (size_t)(bn + r) * DD + c * 32 + cb;
    #pragma unroll
    for (int i = 0; i < 4; i++) a[i] = ((const float4*)xa)[i];
    #pragma unroll
    for (int i = 0; i < 4; i++) b[i] = ((const float4*)wb)[i];
}

__device__ __forceinline__ void sts_chunk(float* stage, const float4 a[4],
                                          const float4 b[4], int tid) {
    const int r = tid >> 1, cb = (tid & 1) * 16;
    float* Ah = stage;
    float* Al = stage + TILEBUF;
    float* Bh = stage + 2 * TILEBUF;
    float* Bl = stage + 3 * TILEBUF;
    #pragma unroll
    for (int i = 0; i < 4; i++) {
        float4 v = a[i], h, l;
        h.x = tr(v.x); l.x = v.x - h.x;
        h.y = tr(v.y); l.y = v.y - h.y;
        h.z = tr(v.z); l.z = v.z - h.z;
        h.w = tr(v.w); l.w = v.w - h.w;
        *(float4*)&Ah[r * STRIDE + cb + i * 4] = h;
        *(float4*)&Al[r * STRIDE + cb + i * 4] = l;
    }
    #pragma unroll
    for (int i = 0; i < 4; i++) {
        float4 v = b[i], h, l;
        h.x = tr(v.x); l.x = v.x - h.x;
        h.y = tr(v.y); l.y = v.y - h.y;
        h.z = tr(v.z); l.z = v.z - h.z;
        h.w = tr(v.w); l.w = v.w - h.w;
        *(float4*)&Bh[r * STRIDE + cb + i * 4] = h;
        *(float4*)&Bl[r * STRIDE + cb + i * 4] = l;
    }
}

__global__ __launch_bounds__(256, 1)
void gemm_kernel(const float* __restrict__ X,
                 const float* __restrict__ bb1, const float* __restrict__ br1,
                 const float* __restrict__ Wb2, const float* __restrict__ Wr2) {
    extern __shared__ float sm[];
    const int tid  = threadIdx.x;
    const int lane = tid & 31, w = tid >> 5;
    const int g = lane >> 2, t = lane & 3;
    const int mw = (w >> 1) * 32;      // warp M offset (4 warps in M)
    const int nw = (w & 1) * 64;       // warp N offset (2 warps in N)
    const int bm = blockIdx.y * 128;
    const int bn = blockIdx.x * 128;
    const int mat = (bn >= HH) ? 1 : 0;
    const int n0  = bn - mat * HH;

    float acc[2][8][4];
    #pragma unroll
    for (int mt = 0; mt < 2; mt++)
        #pragma unroll
        for (int nt = 0; nt < 8; nt++)
            #pragma unroll
            for (int i = 0; i < 4; i++) acc[mt][nt][i] = 0.0f;

    float4 pa[4], pb[4];
    ldg_chunk(pa, pb, X, bm, bn, 0, tid);
    sts_chunk(sm, pa, pb, tid);
    __syncthreads();

    for (int c = 0; c < DD / 32; c++) {
        if (c + 1 < DD / 32) ldg_chunk(pa, pb, X, bm, bn, c + 1, tid);

        const float* stage = sm + (c & 1) * STAGE;
        const float* Ah = stage;
        const float* Al = stage + TILEBUF;
        const float* Bh = stage + 2 * TILEBUF;
        const float* Bl = stage + 3 * TILEBUF;

        #pragma unroll
        for (int kk = 0; kk < 32; kk += 8) {
            float ah[2][4], al[2][4];
            #pragma unroll
            for (int mt = 0; mt < 2; mt++) {
                int r = mw + mt * 16 + g;
                ah[mt][0] = Ah[r * STRIDE + kk + t];
                ah[mt][1] = Ah[(r + 8) * STRIDE + kk + t];
                ah[mt][2] = Ah[r * STRIDE + kk + t + 4];
                ah[mt][3] = Ah[(r + 8) * STRIDE + kk + t + 4];
                al[mt][0] = Al[r * STRIDE + kk + t];
                al[mt][1] = Al[(r + 8) * STRIDE + kk + t];
                al[mt][2] = Al[r * STRIDE + kk + t + 4];
                al[mt][3] = Al[(r + 8) * STRIDE + kk + t + 4];
            }
            float bh[8][2], bl[8][2];
            #pragma unroll
            for (int nt = 0; nt < 8; nt++) {
                int n = nw + nt * 8 + g;
                bh[nt][0] = Bh[n * STRIDE + kk + t];
                bh[nt][1] = Bh[n * STRIDE + kk + t + 4];
                bl[nt][0] = Bl[n * STRIDE + kk + t];
                bl[nt][1] = Bl[n * STRIDE + kk + t + 4];
            }
            // pass 1: hi*hi   (each acc touched once per pass -> 16-deep ILP)
            #pragma unroll
            for (int nt = 0; nt < 8; nt++)
                #pragma unroll
                for (int mt = 0; mt < 2; mt++)
                    mma8(acc[mt][nt], ah[mt], bh[nt][0], bh[nt][1]);
            // pass 2: hi*lo
            #pragma unroll
            for (int nt = 0; nt < 8; nt++)
                #pragma unroll
                for (int mt = 0; mt < 2; mt++)
                    mma8(acc[mt][nt], ah[mt], bl[nt][0], bl[nt][1]);
            // pass 3: lo*hi
            #pragma unroll
            for (int nt = 0; nt < 8; nt++)
                #pragma unroll
                for (int mt = 0; mt < 2; mt++)
                    mma8(acc[mt][nt], al[mt], bh[nt][0], bh[nt][1]);
        }
        __syncthreads();
        if (c + 1 < DD / 32) {
            sts_chunk(sm + ((c + 1) & 1) * STAGE, pa, pb, tid);
            __syncthreads();
        }
    }

    // ---- epilogue: +b1, relu, *W2, row reduce, atomicAdd ----
    const float* __restrict__ b1 = mat ? br1 : bb1;
    const float* __restrict__ W2 = mat ? Wr2 : Wb2;

    #pragma unroll
    for (int mt = 0; mt < 2; mt++) {
        float p0 = 0.0f, p1 = 0.0f;   // rows (g), (g+8) of this m16 tile
        #pragma unroll
        for (int nt = 0; nt < 8; nt++) {
            int n = n0 + nw + nt * 8 + 2 * t;
            float b1a = b1[n], b1b = b1[n + 1];
            float w2a = W2[n], w2b = W2[n + 1];
            p0 = fmaf(fmaxf(acc[mt][nt][0] + b1a, 0.0f), w2a, p0);
            p0 = fmaf(fmaxf(acc[mt][nt][1] + b1b, 0.0f), w2b, p0);
            p1 = fmaf(fmaxf(acc[mt][nt][2] + b1a, 0.0f), w2a, p1);
            p1 = fmaf(fmaxf(acc[mt][nt][3] + b1b, 0.0f), w2b, p1);
        }
        p0 += __shfl_down_sync(0xffffffffu, p0, 2, 4);
        p0 += __shfl_down_sync(0xffffffffu, p0, 1, 4);
        p1 += __shfl_down_sync(0xffffffffu, p1, 2, 4);
        p1 += __shfl_down_sync(0xffffffffu, p1, 1, 4);
        if (t == 0) {
            int row = bm + mw + mt * 16 + g;
            atomicAdd(&g_logits[(size_t)mat * MM + row], p0);
            atomicAdd(&g_logits[(size_t)mat * MM + row + 8], p1);
        }
    }
}

// ---------------------------------------------------------------- 4) soft out
__global__ void soft_kernel(const float* __restrict__ bb2, float* __restrict__ out) {
    int i = blockIdx.x * 256 + threadIdx.x;
    if (i < MM) {
        int b = i >> 12;
        int t = i & (TT - 1);
        out[i] = g_logits[t * BB + b] + bb2[0];
    }
}

// ---------------------------------------------------------------- 5) LIF scan
__global__ void scan_kernel(const float* __restrict__ bb2,
                            const float* __restrict__ br2,
                            float* __restrict__ out_hard) {
    __shared__ float sx[512 * BB];
    __shared__ float sr[512 * BB];
    const int tid = threadIdx.x;
    const float b2 = bb2[0], r2 = br2[0];
    float v = 0.0f;

    for (int t0 = 0; t0 < TT; t0 += 512) {
        __syncthreads();
        for (int i = tid; i < 512 * BB; i += 128) {
            sx[i] = g_logits[t0 * BB + i];
            sr[i] = g_logits[MM + t0 * BB + i];
        }
        __syncthreads();
        if (tid < BB) {
            #pragma unroll 4
            for (int tt = 0; tt < 512; tt++) {
                float x  = sx[tt * BB + tid] + b2;
                bool  rm = (sr[tt * BB + tid] + r2) > 0.0f;
                v = v + (x - v) * 0.5f;                 // leaky integrate (tau=2)
                float s = (v >= 1.0f) ? 1.0f : 0.0f;    // fire
                out_hard[tid * TT + t0 + tt] = s;
                if (v >= 1.0f) v = 0.0f;                // hard reset on spike
                if (rm)        v = 0.0f;                // conditional forced reset
            }
        }
    }
}

// ----------------------------------------------------------------------------
extern "C" void kernel_launch(void* const* d_in, const int* in_sizes, int n_in,
                              void* d_out, int out_size) {
    const float* hidden = (const float*)d_in[0];
    const float* Wb1    = (const float*)d_in[1];
    const float* bb1    = (const float*)d_in[2];
    const float* Wb2    = (const float*)d_in[3];
    const float* bb2    = (const float*)d_in[4];
    const float* Wr1    = (const float*)d_in[5];
    const float* br1    = (const float*)d_in[6];
    const float* Wr2    = (const float*)d_in[7];
    const float* br2    = (const float*)d_in[8];
    float* out = (float*)d_out;

    zero_kernel<<<(2 * MM + 255) / 256, 256>>>();

    {
        dim3 gw(NN / 32, DD / 32);
        prep_w<<<gw, 256>>>(Wb1, Wr1);
    }

    cudaFuncSetAttribute(gemm_kernel, cudaFuncAttributeMaxDynamicSharedMemorySize,
                         SMEM_BYTES);
    {
        dim3 gg(NN / 128, MM / 128);   // (64, 128) = 8192 CTAs
        gemm_kernel<<<gg, 256, SMEM_BYTES>>>(hidden, bb1, br1, Wb2, Wr2);
    }

    soft_kernel<<<MM / 256, 256>>>(bb2, out);
    scan_kernel<<<1, 128>>>(bb2, br2, out + MM);
}